// round 1
// baseline (speedup 1.0000x reference)
#include <cuda_runtime.h>
#include <math.h>

#define BATCH 16
#define CIN   64
#define LEN   1024
#define HID   1024
#define OUTC  512
#define EPS   1e-5f
#define MTOT  (BATCH*LEN)   // 16384

#define GBM 128
#define GBN 128
#define GBK 16
#define GTM 8
#define GTN 8
#define NTHR 256

// ---------------- scratch (static device globals; no allocation) ----------------
__device__ float g_h0[MTOT*HID];          // 64 MB  (projection output)
__device__ float g_h1[MTOT*HID];          // 64 MB  (kan1 output / gelu output)
__device__ float g_h2[MTOT*OUTC];         // 32 MB  (kan2 output / ln2 output)
__device__ float g_Bp1[3*HID*HID];        // 12 MB  repacked coeffs1 orders 1..3, [i][c][o]
__device__ float g_Bp2[3*HID*OUTC];       //  6 MB  repacked coeffs2
__device__ float g_c01[HID];              // bias1 + sum_c coeffs1[o,c,0]
__device__ float g_c02[OUTC];

// ---------------- coeff repack: coeffs[o,c,i] -> Bp[i][c][o] for i=1..3 ----------------
template<int STAGE>
__global__ void repack_kernel(const float* __restrict__ coeffs) {
    const int outc = (STAGE == 1) ? HID : OUTC;
    float* Bp = (STAGE == 1) ? (float*)g_Bp1 : (float*)g_Bp2;
    int o = blockIdx.x * blockDim.x + threadIdx.x;   // over outc (coalesced writes)
    int c = blockIdx.y;
    float4 v = *reinterpret_cast<const float4*>(coeffs + ((size_t)o * HID + c) * 4);
    Bp[(size_t)0 * HID * outc + (size_t)c * outc + o] = v.y;
    Bp[(size_t)1 * HID * outc + (size_t)c * outc + o] = v.z;
    Bp[(size_t)2 * HID * outc + (size_t)c * outc + o] = v.w;
}

// order-0 term is constant: c0[o] = bias[o] + sum_c coeffs[o,c,0]
template<int STAGE>
__global__ void c0_kernel(const float* __restrict__ coeffs, const float* __restrict__ bias) {
    float* c0 = (STAGE == 1) ? (float*)g_c01 : (float*)g_c02;
    int o = blockIdx.x;
    __shared__ float red[256];
    float s = 0.f;
    for (int c = threadIdx.x; c < HID; c += 256)
        s += coeffs[((size_t)o * HID + c) * 4];
    red[threadIdx.x] = s; __syncthreads();
    #pragma unroll
    for (int st = 128; st > 0; st >>= 1) {
        if (threadIdx.x < st) red[threadIdx.x] += red[threadIdx.x + st];
        __syncthreads();
    }
    if (threadIdx.x == 0) c0[o] = red[0] + bias[o];
}

// ---------------- projection GEMM: h0[m,n] = sum_k x[b,k,l]*W[k,n] + bias[n] ----------------
__global__ void gemm_proj_kernel(const float* __restrict__ x, const float* __restrict__ W,
                                 const float* __restrict__ bias) {
    __shared__ float As[GBK][GBM];
    __shared__ float Bs[GBK][GBN];
    const int m0 = blockIdx.y * GBM, n0 = blockIdx.x * GBN;
    const int tid = threadIdx.x;
    const int tx = tid & 15, ty = tid >> 4;
    float acc[GTM][GTN] = {};

    for (int kt = 0; kt < CIN; kt += GBK) {
        #pragma unroll
        for (int ii = 0; ii < 8; ii++) {
            int idx = tid + ii * NTHR;         // 0..2047
            int mm = idx & (GBM - 1);          // consecutive tid -> consecutive l: coalesced
            int kk = idx >> 7;
            int m = m0 + mm;
            As[kk][mm] = x[((size_t)(m >> 10) * CIN + (kt + kk)) * LEN + (m & 1023)];
        }
        #pragma unroll
        for (int ii = 0; ii < 8; ii++) {
            int idx = tid + ii * NTHR;
            int nn = idx & (GBN - 1);
            int kk = idx >> 7;
            Bs[kk][nn] = W[(size_t)(kt + kk) * HID + n0 + nn];
        }
        __syncthreads();
        #pragma unroll
        for (int kk = 0; kk < GBK; kk++) {
            float a[GTM], bb[GTN];
            #pragma unroll
            for (int i = 0; i < GTM; i++) a[i] = As[kk][ty * GTM + i];
            #pragma unroll
            for (int j = 0; j < GTN; j++) bb[j] = Bs[kk][tx * GTN + j];
            #pragma unroll
            for (int i = 0; i < GTM; i++)
                #pragma unroll
                for (int j = 0; j < GTN; j++)
                    acc[i][j] = fmaf(a[i], bb[j], acc[i][j]);
        }
        __syncthreads();
    }
    #pragma unroll
    for (int i = 0; i < GTM; i++) {
        int m = m0 + ty * GTM + i;
        float* Cp = g_h0 + (size_t)m * HID + n0 + tx * GTN;
        #pragma unroll
        for (int j = 0; j < GTN; j++) Cp[j] = acc[i][j] + bias[n0 + tx * GTN + j];
    }
}

// ---------------- fused TaylorKAN GEMM: C = c0 + A@B1 + A^2@B2 + A^3@B3 ----------------
template<int STAGE>
__global__ void gemm_kan_kernel() {
    const int N        = (STAGE == 1) ? HID : OUTC;
    const float* A     = (STAGE == 1) ? (const float*)g_h0  : (const float*)g_h1;
    const float* Bp    = (STAGE == 1) ? (const float*)g_Bp1 : (const float*)g_Bp2;
    const float* c0    = (STAGE == 1) ? (const float*)g_c01 : (const float*)g_c02;
    float* C           = (STAGE == 1) ? (float*)g_h1 : (float*)g_h2;

    __shared__ float As[GBK][GBM];
    __shared__ float Bs[3][GBK][GBN];
    const int m0 = blockIdx.y * GBM, n0 = blockIdx.x * GBN;
    const int tid = threadIdx.x;
    const int tx = tid & 15, ty = tid >> 4;
    float acc[GTM][GTN] = {};

    for (int kt = 0; kt < HID; kt += GBK) {
        // A tile (128x16), float4 along k, store transposed
        #pragma unroll
        for (int ii = 0; ii < 2; ii++) {
            int idx = tid + ii * NTHR;   // 0..511
            int mm = idx >> 2;
            int kq = idx & 3;
            float4 v = *reinterpret_cast<const float4*>(A + (size_t)(m0 + mm) * HID + kt + kq * 4);
            As[kq * 4 + 0][mm] = v.x;
            As[kq * 4 + 1][mm] = v.y;
            As[kq * 4 + 2][mm] = v.z;
            As[kq * 4 + 3][mm] = v.w;
        }
        // 3 B tiles (16x128 each), float4
        #pragma unroll
        for (int ii = 0; ii < 6; ii++) {
            int idx = tid + ii * NTHR;   // 0..1535 float4s
            int im  = idx >> 9;
            int rem = idx & 511;
            int kk  = rem >> 5;
            int nq  = rem & 31;
            float4 v = *reinterpret_cast<const float4*>(
                Bp + ((size_t)im * HID + kt + kk) * N + n0 + nq * 4);
            *reinterpret_cast<float4*>(&Bs[im][kk][nq * 4]) = v;
        }
        __syncthreads();
        #pragma unroll
        for (int kk = 0; kk < GBK; kk++) {
            float a[GTM], b1[GTN], b2[GTN], b3[GTN];
            #pragma unroll
            for (int i = 0; i < GTM; i++) a[i] = As[kk][ty * GTM + i];
            #pragma unroll
            for (int j = 0; j < GTN; j++) {
                b1[j] = Bs[0][kk][tx * GTN + j];
                b2[j] = Bs[1][kk][tx * GTN + j];
                b3[j] = Bs[2][kk][tx * GTN + j];
            }
            #pragma unroll
            for (int i = 0; i < GTM; i++) {
                float av = a[i];
                float av2 = av * av;
                float av3 = av2 * av;
                #pragma unroll
                for (int j = 0; j < GTN; j++)
                    acc[i][j] = fmaf(av,  b1[j],
                                fmaf(av2, b2[j],
                                fmaf(av3, b3[j], acc[i][j])));
            }
        }
        __syncthreads();
    }
    #pragma unroll
    for (int i = 0; i < GTM; i++) {
        int m = m0 + ty * GTM + i;
        float* Cp = C + (size_t)m * N + n0 + tx * GTN;
        #pragma unroll
        for (int j = 0; j < GTN; j++) Cp[j] = acc[i][j] + c0[n0 + tx * GTN + j];
    }
}

// ---------------- LayerNorm (+ exact GELU) ----------------
__device__ __forceinline__ float block_reduce_sum(float v, float* red, int t) {
    red[t] = v; __syncthreads();
    #pragma unroll
    for (int st = 128; st > 0; st >>= 1) {
        if (t < st) red[t] += red[t + st];
        __syncthreads();
    }
    float r = red[0];
    __syncthreads();
    return r;
}

__global__ void ln_gelu_kernel(const float* __restrict__ g, const float* __restrict__ beta) {
    __shared__ float red[256];
    int t = threadIdx.x;
    float* p = g_h1 + (size_t)blockIdx.x * HID;
    float v[4];
    float s = 0.f;
    #pragma unroll
    for (int i = 0; i < 4; i++) { v[i] = p[t + i * 256]; s += v[i]; }
    float mu = block_reduce_sum(s, red, t) * (1.f / HID);
    float s2 = 0.f;
    #pragma unroll
    for (int i = 0; i < 4; i++) { float d = v[i] - mu; s2 += d * d; }
    float var = block_reduce_sum(s2, red, t) * (1.f / HID);
    float rstd = rsqrtf(var + EPS);
    #pragma unroll
    for (int i = 0; i < 4; i++) {
        int o = t + i * 256;
        float y = (v[i] - mu) * rstd * g[o] + beta[o];
        p[o] = 0.5f * y * (1.f + erff(y * 0.70710678118654752f));  // exact gelu
    }
}

__global__ void ln2_kernel(const float* __restrict__ g, const float* __restrict__ beta) {
    __shared__ float red[256];
    int t = threadIdx.x;
    float* p = g_h2 + (size_t)blockIdx.x * OUTC;
    float v[2];
    float s = 0.f;
    #pragma unroll
    for (int i = 0; i < 2; i++) { v[i] = p[t + i * 256]; s += v[i]; }
    float mu = block_reduce_sum(s, red, t) * (1.f / OUTC);
    float s2 = 0.f;
    #pragma unroll
    for (int i = 0; i < 2; i++) { float d = v[i] - mu; s2 += d * d; }
    float rstd = rsqrtf(block_reduce_sum(s2, red, t) * (1.f / OUTC) + EPS);
    #pragma unroll
    for (int i = 0; i < 2; i++) {
        int o = t + i * 256;
        p[o] = (v[i] - mu) * rstd * g[o] + beta[o];
    }
}

// ---------------- mean over L (deterministic serial per (b,o)) ----------------
__global__ void reduce_kernel(float* __restrict__ out) {
    int b = blockIdx.x, o = threadIdx.x;   // 512 threads
    const float* p = g_h2 + (size_t)b * LEN * OUTC + o;
    float s = 0.f;
    #pragma unroll 8
    for (int l = 0; l < LEN; l++) s += p[(size_t)l * OUTC];
    out[b * OUTC + o] = s * (1.f / LEN);
}

// ---------------- launch ----------------
extern "C" void kernel_launch(void* const* d_in, const int* in_sizes, int n_in,
                              void* d_out, int out_size) {
    const float* x       = (const float*)d_in[0];
    const float* W_in    = (const float*)d_in[1];
    const float* b_in    = (const float*)d_in[2];
    const float* coeffs1 = (const float*)d_in[3];
    const float* bias1   = (const float*)d_in[4];
    const float* g1      = (const float*)d_in[5];
    const float* beta1   = (const float*)d_in[6];
    const float* coeffs2 = (const float*)d_in[7];
    const float* bias2   = (const float*)d_in[8];
    const float* g2      = (const float*)d_in[9];
    const float* beta2   = (const float*)d_in[10];
    float* out = (float*)d_out;

    repack_kernel<1><<<dim3(HID / 256, HID), 256>>>(coeffs1);
    c0_kernel<1><<<HID, 256>>>(coeffs1, bias1);
    repack_kernel<2><<<dim3(OUTC / 256, HID), 256>>>(coeffs2);
    c0_kernel<2><<<OUTC, 256>>>(coeffs2, bias2);

    gemm_proj_kernel<<<dim3(HID / GBN, MTOT / GBM), NTHR>>>(x, W_in, b_in);
    gemm_kan_kernel<1><<<dim3(HID / GBN, MTOT / GBM), NTHR>>>();
    ln_gelu_kernel<<<MTOT, 256>>>(g1, beta1);
    gemm_kan_kernel<2><<<dim3(OUTC / GBN, MTOT / GBM), NTHR>>>();
    ln2_kernel<<<MTOT, 256>>>(g2, beta2);
    reduce_kernel<<<BATCH, OUTC>>>(out);
}

// round 3
// speedup vs baseline: 2.8470x; 2.8470x over previous
#include <cuda_runtime.h>
#include <cuda_bf16.h>
#include <cstdint>
#include <math.h>

#define BATCH 16
#define CIN   64
#define LEN   1024
#define HID   1024
#define OUTC  512
#define EPS   1e-5f
#define MTOT  (BATCH*LEN)   // 16384

// GEMM tiling
#define KC     32            // source-k per stage
#define NK     (HID/KC)      // 32 stages
#define A_ST   49152         // 6 planes * 128 rows * 64B
#define B_ST   49152
#define STG    (A_ST + B_ST) // 96KB per stage
#define SMEM_GEMM (2*STG)    // 192KB

// fp32 SIMT proj tile params
#define GBM 128
#define GBN 128
#define GBK 16
#define GTM 8
#define GTN 8
#define NTHR 256

// ---------------- scratch ----------------
__device__ __align__(16)  float g_h0[MTOT*HID];
__device__ __align__(16)  float g_h1[MTOT*HID];
__device__ __align__(16)  float g_h2[MTOT*OUTC];
__device__ __align__(128) __nv_bfloat16 g_A6a[(size_t)MTOT*6144];   // 192MB
__device__ __align__(128) __nv_bfloat16 g_A6b[(size_t)MTOT*6144];   // 192MB
__device__ __align__(128) __nv_bfloat16 g_B6a[(size_t)6*HID*1024];  // 12MB
__device__ __align__(128) __nv_bfloat16 g_B6b[(size_t)6*OUTC*1024]; // 6MB
__device__ float g_c01[HID];
__device__ float g_c02[OUTC];

// ---------------- helpers ----------------
__device__ __forceinline__ uint32_t smem_u32(const void* p) {
    uint32_t a;
    asm("{ .reg .u64 t; cvta.to.shared.u64 t, %1; cvt.u32.u64 %0, t; }" : "=r"(a) : "l"(p));
    return a;
}

#define LDSM_X4(r, addr) \
    asm volatile("ldmatrix.sync.aligned.m8n8.x4.shared.b16 {%0,%1,%2,%3}, [%4];" \
        : "=r"((r)[0]), "=r"((r)[1]), "=r"((r)[2]), "=r"((r)[3]) : "r"(addr))
#define LDSM_X2(r, addr) \
    asm volatile("ldmatrix.sync.aligned.m8n8.x2.shared.b16 {%0,%1}, [%2];" \
        : "=r"((r)[0]), "=r"((r)[1]) : "r"(addr))
#define MMA16816(d, a, b) \
    asm volatile("mma.sync.aligned.m16n8k16.row.col.f32.bf16.bf16.f32 " \
        "{%0,%1,%2,%3}, {%4,%5,%6,%7}, {%8,%9}, {%0,%1,%2,%3};" \
        : "+f"((d)[0]), "+f"((d)[1]), "+f"((d)[2]), "+f"((d)[3]) \
        : "r"((a)[0]), "r"((a)[1]), "r"((a)[2]), "r"((a)[3]), "r"((b)[0]), "r"((b)[1]))

__device__ __forceinline__ void split6(__nv_bfloat16* p, float x) {
    float x2 = x * x, x3 = x2 * x;
    __nv_bfloat16 h;
    h = __float2bfloat16(x);  p[0]    = h; p[1024] = __float2bfloat16(x  - __bfloat162float(h));
    h = __float2bfloat16(x2); p[2048] = h; p[3072] = __float2bfloat16(x2 - __bfloat162float(h));
    h = __float2bfloat16(x3); p[4096] = h; p[5120] = __float2bfloat16(x3 - __bfloat162float(h));
}

// ---------------- B repack + c0 ----------------
template<int STAGE>
__global__ void repackB_kernel(const float* __restrict__ coeffs, const float* __restrict__ bias) {
    const int N = (STAGE == 1) ? HID : OUTC;
    __nv_bfloat16* B6 = (STAGE == 1) ? g_B6a : g_B6b;
    float* c0         = (STAGE == 1) ? g_c01 : g_c02;
    int o = blockIdx.x;
    __shared__ float red[256];
    float s = 0.f;
    #pragma unroll
    for (int it = 0; it < 4; it++) {
        int c = threadIdx.x + it * 256;
        float4 v = *reinterpret_cast<const float4*>(coeffs + ((size_t)o * HID + c) * 4);
        s += v.x;
        size_t base = (size_t)o * 1024 + c;
        size_t ps = (size_t)N * 1024;
        __nv_bfloat16 h;
        h = __float2bfloat16(v.y); B6[0*ps + base] = h; B6[1*ps + base] = __float2bfloat16(v.y - __bfloat162float(h));
        h = __float2bfloat16(v.z); B6[2*ps + base] = h; B6[3*ps + base] = __float2bfloat16(v.z - __bfloat162float(h));
        h = __float2bfloat16(v.w); B6[4*ps + base] = h; B6[5*ps + base] = __float2bfloat16(v.w - __bfloat162float(h));
    }
    red[threadIdx.x] = s; __syncthreads();
    #pragma unroll
    for (int st = 128; st > 0; st >>= 1) {
        if (threadIdx.x < st) red[threadIdx.x] += red[threadIdx.x + st];
        __syncthreads();
    }
    if (threadIdx.x == 0) c0[o] = red[0] + bias[o];
}

// ---------------- projection GEMM (fp32 SIMT; 2.1 GF) ----------------
__global__ void gemm_proj_kernel(const float* __restrict__ x, const float* __restrict__ W,
                                 const float* __restrict__ bias) {
    __shared__ float As[GBK][GBM];
    __shared__ float Bs[GBK][GBN];
    const int m0 = blockIdx.y * GBM, n0 = blockIdx.x * GBN;
    const int tid = threadIdx.x;
    const int tx = tid & 15, ty = tid >> 4;
    float acc[GTM][GTN] = {};
    for (int kt = 0; kt < CIN; kt += GBK) {
        #pragma unroll
        for (int ii = 0; ii < 8; ii++) {
            int idx = tid + ii * NTHR;
            int mm = idx & (GBM - 1);
            int kk = idx >> 7;
            int m = m0 + mm;
            As[kk][mm] = x[((size_t)(m >> 10) * CIN + (kt + kk)) * LEN + (m & 1023)];
        }
        #pragma unroll
        for (int ii = 0; ii < 8; ii++) {
            int idx = tid + ii * NTHR;
            int nn = idx & (GBN - 1);
            int kk = idx >> 7;
            Bs[kk][nn] = W[(size_t)(kt + kk) * HID + n0 + nn];
        }
        __syncthreads();
        #pragma unroll
        for (int kk = 0; kk < GBK; kk++) {
            float a[GTM], bb[GTN];
            #pragma unroll
            for (int i = 0; i < GTM; i++) a[i] = As[kk][ty * GTM + i];
            #pragma unroll
            for (int j = 0; j < GTN; j++) bb[j] = Bs[kk][tx * GTN + j];
            #pragma unroll
            for (int i = 0; i < GTM; i++)
                #pragma unroll
                for (int j = 0; j < GTN; j++)
                    acc[i][j] = fmaf(a[i], bb[j], acc[i][j]);
        }
        __syncthreads();
    }
    #pragma unroll
    for (int i = 0; i < GTM; i++) {
        int m = m0 + ty * GTM + i;
        float* Cp = g_h0 + (size_t)m * HID + n0 + tx * GTN;
        #pragma unroll
        for (int j = 0; j < GTN; j++) Cp[j] = acc[i][j] + bias[n0 + tx * GTN + j];
    }
}

// ---------------- split A for kan1 ----------------
__global__ void splitA_kernel() {
    size_t idx = (size_t)blockIdx.x * 256 + threadIdx.x;
    float x = g_h0[idx];
    int m = (int)(idx >> 10), k = (int)(idx & 1023);
    split6(g_A6a + (size_t)m * 6144 + k, x);
}

// ---------------- LN + exact GELU + split ----------------
__device__ __forceinline__ float block_reduce_sum(float v, float* red, int t) {
    red[t] = v; __syncthreads();
    #pragma unroll
    for (int st = 128; st > 0; st >>= 1) {
        if (t < st) red[t] += red[t + st];
        __syncthreads();
    }
    float r = red[0];
    __syncthreads();
    return r;
}

__global__ void ln_gelu_split_kernel(const float* __restrict__ g, const float* __restrict__ beta) {
    __shared__ float red[256];
    int t = threadIdx.x;
    const float* p = g_h1 + (size_t)blockIdx.x * HID;
    float v[4];
    float s = 0.f;
    #pragma unroll
    for (int i = 0; i < 4; i++) { v[i] = p[t + i * 256]; s += v[i]; }
    float mu = block_reduce_sum(s, red, t) * (1.f / HID);
    float s2 = 0.f;
    #pragma unroll
    for (int i = 0; i < 4; i++) { float d = v[i] - mu; s2 += d * d; }
    float rstd = rsqrtf(block_reduce_sum(s2, red, t) * (1.f / HID) + EPS);
    __nv_bfloat16* Ap = g_A6b + (size_t)blockIdx.x * 6144;
    #pragma unroll
    for (int i = 0; i < 4; i++) {
        int o = t + i * 256;
        float y = (v[i] - mu) * rstd * g[o] + beta[o];
        y = 0.5f * y * (1.f + erff(y * 0.70710678118654752f));
        split6(Ap + o, y);
    }
}

// ---------------- fused KAN GEMM via mma.sync ----------------
__device__ __forceinline__ void load_stage_kan(const __nv_bfloat16* A6, const __nv_bfloat16* B6,
                                               int N, int m0, int n0, int kt,
                                               uint32_t bufA, uint32_t bufB, int tid) {
    int k0 = kt * KC;
    #pragma unroll
    for (int i = 0; i < 12; i++) {
        int id = tid + i * 256;
        int plane = id >> 9;
        int r = id & 511;
        int m = r >> 2, j = r & 3;
        const void* gp = (const void*)(A6 + (size_t)(m0 + m) * 6144 + plane * 1024 + k0 + j * 8);
        uint32_t sp = bufA + plane * 8192 + m * 64 + (((uint32_t)(j ^ ((m >> 1) & 3))) << 4);
        asm volatile("cp.async.cg.shared.global [%0], [%1], 16;" :: "r"(sp), "l"(gp));
    }
    #pragma unroll
    for (int i = 0; i < 12; i++) {
        int id = tid + i * 256;
        int plane = id >> 9;
        int r = id & 511;
        int n = r >> 2, j = r & 3;
        const void* gp = (const void*)(B6 + (size_t)plane * N * 1024 + (size_t)(n0 + n) * 1024 + k0 + j * 8);
        uint32_t sp = bufB + plane * 8192 + n * 64 + (((uint32_t)(j ^ ((n >> 1) & 3))) << 4);
        asm volatile("cp.async.cg.shared.global [%0], [%1], 16;" :: "r"(sp), "l"(gp));
    }
    asm volatile("cp.async.commit_group;" ::: "memory");
}

template<int STAGE>
__global__ void __launch_bounds__(256, 1) gemm_kan_mma() {
    const int N            = (STAGE == 1) ? HID : OUTC;
    const __nv_bfloat16* A6 = (STAGE == 1) ? g_A6a : g_A6b;
    const __nv_bfloat16* B6 = (STAGE == 1) ? g_B6a : g_B6b;
    const float* c0v        = (STAGE == 1) ? g_c01 : g_c02;
    float* C                = (STAGE == 1) ? g_h1 : g_h2;

    extern __shared__ char smem[];
    uint32_t sb = smem_u32(smem);
    int tid = threadIdx.x, lane = tid & 31, w = tid >> 5;
    int wm = w >> 2, wn = w & 3;
    int m0 = blockIdx.y * 128, n0 = blockIdx.x * 128;

    float acc[4][4][4] = {};

    uint32_t aOff[4], bOff[4];
    int aSw[4], bSw[4];
    int hiA = lane >> 4;          // 0/1 -> k/k+8 matrix
    int hiB = (lane >> 3) & 1;
    #pragma unroll
    for (int s = 0; s < 4; s++) {
        int r = wm * 64 + s * 16 + (lane & 15);
        aOff[s] = (uint32_t)r * 64;
        aSw[s] = (r >> 1) & 3;
    }
    #pragma unroll
    for (int t = 0; t < 4; t++) {
        int r = wn * 32 + t * 8 + (lane & 7);
        bOff[t] = (uint32_t)r * 64;
        bSw[t] = (r >> 1) & 3;
    }

    load_stage_kan(A6, B6, N, m0, n0, 0, sb, sb + A_ST, tid);

    for (int kt = 0; kt < NK; kt++) {
        uint32_t bufA = sb + (uint32_t)(kt & 1) * STG;
        uint32_t bufB = bufA + A_ST;
        if (kt + 1 < NK) {
            uint32_t nb = sb + (uint32_t)((kt + 1) & 1) * STG;
            load_stage_kan(A6, B6, N, m0, n0, kt + 1, nb, nb + A_ST, tid);
            asm volatile("cp.async.wait_group 1;" ::: "memory");
        } else {
            asm volatile("cp.async.wait_group 0;" ::: "memory");
        }
        __syncthreads();

        #pragma unroll
        for (int kk = 0; kk < 2; kk++) {
            #pragma unroll
            for (int o = 0; o < 3; o++) {
                uint32_t bh[4][2], bl[4][2];
                #pragma unroll
                for (int t = 0; t < 4; t++) {
                    uint32_t col = (uint32_t)((kk * 2 + hiB) ^ bSw[t]) << 4;
                    LDSM_X2(bh[t], bufB + (2 * o) * 8192 + bOff[t] + col);
                    LDSM_X2(bl[t], bufB + (2 * o + 1) * 8192 + bOff[t] + col);
                }
                #pragma unroll
                for (int s = 0; s < 4; s++) {
                    uint32_t col = (uint32_t)((kk * 2 + hiA) ^ aSw[s]) << 4;
                    uint32_t ah[4], al[4];
                    LDSM_X4(ah, bufA + (2 * o) * 8192 + aOff[s] + col);
                    LDSM_X4(al, bufA + (2 * o + 1) * 8192 + aOff[s] + col);
                    #pragma unroll
                    for (int t = 0; t < 4; t++) {
                        MMA16816(acc[s][t], ah, bh[t]);
                        MMA16816(acc[s][t], al, bh[t]);
                        MMA16816(acc[s][t], ah, bl[t]);
                    }
                }
            }
        }
        __syncthreads();
    }

    // epilogue
    #pragma unroll
    for (int t = 0; t < 4; t++) {
        int col = n0 + wn * 32 + t * 8 + (lane & 3) * 2;
        float c0a = c0v[col], c0b = c0v[col + 1];
        #pragma unroll
        for (int s = 0; s < 4; s++) {
            int r0 = m0 + wm * 64 + s * 16 + (lane >> 2);
            float2 v0 = make_float2(acc[s][t][0] + c0a, acc[s][t][1] + c0b);
            float2 v1 = make_float2(acc[s][t][2] + c0a, acc[s][t][3] + c0b);
            *reinterpret_cast<float2*>(C + (size_t)r0 * N + col) = v0;
            *reinterpret_cast<float2*>(C + (size_t)(r0 + 8) * N + col) = v1;
        }
    }
}

// ---------------- LayerNorm 2 ----------------
__global__ void ln2_kernel(const float* __restrict__ g, const float* __restrict__ beta) {
    __shared__ float red[256];
    int t = threadIdx.x;
    float* p = g_h2 + (size_t)blockIdx.x * OUTC;
    float v[2];
    float s = 0.f;
    #pragma unroll
    for (int i = 0; i < 2; i++) { v[i] = p[t + i * 256]; s += v[i]; }
    float mu = block_reduce_sum(s, red, t) * (1.f / OUTC);
    float s2 = 0.f;
    #pragma unroll
    for (int i = 0; i < 2; i++) { float d = v[i] - mu; s2 += d * d; }
    float rstd = rsqrtf(block_reduce_sum(s2, red, t) * (1.f / OUTC) + EPS);
    #pragma unroll
    for (int i = 0; i < 2; i++) {
        int o = t + i * 256;
        p[o] = (v[i] - mu) * rstd * g[o] + beta[o];
    }
}

// ---------------- mean over L ----------------
__global__ void reduce_kernel(float* __restrict__ out) {
    int b = blockIdx.x, o = threadIdx.x;
    const float* p = g_h2 + (size_t)b * LEN * OUTC + o;
    float s = 0.f;
    #pragma unroll 8
    for (int l = 0; l < LEN; l++) s += p[(size_t)l * OUTC];
    out[b * OUTC + o] = s * (1.f / LEN);
}

// ---------------- launch ----------------
extern "C" void kernel_launch(void* const* d_in, const int* in_sizes, int n_in,
                              void* d_out, int out_size) {
    const float* x       = (const float*)d_in[0];
    const float* W_in    = (const float*)d_in[1];
    const float* b_in    = (const float*)d_in[2];
    const float* coeffs1 = (const float*)d_in[3];
    const float* bias1   = (const float*)d_in[4];
    const float* g1      = (const float*)d_in[5];
    const float* beta1   = (const float*)d_in[6];
    const float* coeffs2 = (const float*)d_in[7];
    const float* bias2   = (const float*)d_in[8];
    const float* g2      = (const float*)d_in[9];
    const float* beta2   = (const float*)d_in[10];
    float* out = (float*)d_out;

    cudaFuncSetAttribute(gemm_kan_mma<1>, cudaFuncAttributeMaxDynamicSharedMemorySize, SMEM_GEMM);
    cudaFuncSetAttribute(gemm_kan_mma<2>, cudaFuncAttributeMaxDynamicSharedMemorySize, SMEM_GEMM);

    repackB_kernel<1><<<HID, 256>>>(coeffs1, bias1);
    repackB_kernel<2><<<OUTC, 256>>>(coeffs2, bias2);

    gemm_proj_kernel<<<dim3(HID / GBN, MTOT / GBM), NTHR>>>(x, W_in, b_in);
    splitA_kernel<<<MTOT * HID / 256, 256>>>();
    gemm_kan_mma<1><<<dim3(HID / 128, MTOT / 128), 256, SMEM_GEMM>>>();
    ln_gelu_split_kernel<<<MTOT, 256>>>(g1, beta1);
    gemm_kan_mma<2><<<dim3(OUTC / 128, MTOT / 128), 256, SMEM_GEMM>>>();
    ln2_kernel<<<MTOT, 256>>>(g2, beta2);
    reduce_kernel<<<BATCH, OUTC>>>(out);
}